// round 1
// baseline (speedup 1.0000x reference)
#include <cuda_runtime.h>
#include <math.h>

#define N_NODES 50000
#define FIN 128
#define H1 8
#define C1 16
#define F1 128            // H1*C1
#define E_MAX 800000
#define ET_MAX (E_MAX + N_NODES)
#define NEG_SLOPE 0.2f

// ------------------------- scratch (static device globals) -------------------------
__device__ float g_h1[N_NODES * F1];       // x @ W1
__device__ float g_agg1[N_NODES * F1];     // layer1 aggregation -> elu in place
__device__ float g_asrc[N_NODES * H1];
__device__ float g_adst[N_NODES * H1];
__device__ float g_e1[ET_MAX * H1];        // per-edge e, then ee
__device__ float g_m1[N_NODES * H1];
__device__ float g_s1[N_NODES * H1];
__device__ float g_h2[N_NODES * 2];
__device__ float g_a2s[N_NODES];
__device__ float g_a2d[N_NODES];
__device__ float g_e2[ET_MAX];
__device__ float g_m2[N_NODES];
__device__ float g_s2[N_NODES];
__device__ int   g_src[ET_MAX];
__device__ int   g_dst[ET_MAX];
__device__ int   g_is64;

// ------------------------- helpers -------------------------
__device__ __forceinline__ void atomicMaxF(float* addr, float v) {
    if (v >= 0.f) atomicMax((int*)addr, __float_as_int(v));
    else          atomicMin((unsigned int*)addr, __float_as_uint(v));
}

__device__ __forceinline__ void redAdd4(float* addr, float a, float b, float c, float d) {
    asm volatile("red.global.add.v4.f32 [%0], {%1,%2,%3,%4};"
                 :: "l"(addr), "f"(a), "f"(b), "f"(c), "f"(d) : "memory");
}
__device__ __forceinline__ void redAdd2(float* addr, float a, float b) {
    asm volatile("red.global.add.v2.f32 [%0], {%1,%2};"
                 :: "l"(addr), "f"(a), "f"(b) : "memory");
}

#define NEG_INF __int_as_float(0xff800000)

// ------------------------- dtype probe: int64 vs int32 edge_index -------------------------
__global__ void probe_kernel(const void* ei) {
    const long long* p = (const long long*)ei;
    int bad = 0;
    for (int i = threadIdx.x; i < 2048; i += 256) {
        long long v = p[i];
        if (v < 0 || v >= (long long)N_NODES) bad = 1;
    }
    bad = __syncthreads_or(bad);
    if (threadIdx.x == 0) g_is64 = bad ? 0 : 1;
}

// convert edge list to int32 and append self-loops
__global__ void convert_kernel(const void* ei, int E, int ET) {
    int i = blockIdx.x * blockDim.x + threadIdx.x;
    if (i >= ET) return;
    int s, d;
    if (i < E) {
        if (g_is64) {
            const long long* p = (const long long*)ei;
            s = (int)p[i]; d = (int)p[E + i];
        } else {
            const int* p = (const int*)ei;
            s = p[i]; d = p[E + i];
        }
    } else {
        s = d = i - E;
    }
    g_src[i] = s;
    g_dst[i] = d;
}

// ------------------------- init -------------------------
__global__ void init_kernel(float* out, const float* __restrict__ b2) {
    int i = blockIdx.x * blockDim.x + threadIdx.x;
    if (i < N_NODES * F1) g_agg1[i] = 0.f;
    if (i < N_NODES * H1) { g_m1[i] = NEG_INF; g_s1[i] = 0.f; }
    if (i < N_NODES)      { g_m2[i] = NEG_INF; g_s2[i] = 0.f; }
    if (i < N_NODES * 2)  out[i] = b2[i & 1];
}

// ------------------------- GEMM: h1 = x @ W1  (M x 128 x 128) -------------------------
#define GM_BM 64
#define GM_BK 32
__global__ void gemm1_kernel(const float* __restrict__ X, const float* __restrict__ W, int M) {
    __shared__ __align__(16) float Xs[GM_BM][GM_BK + 1];
    __shared__ __align__(16) float Ws[GM_BK][F1 + 4];
    int tid = threadIdx.x;
    int tx = tid & 15;       // col group (8 cols each)
    int ty = tid >> 4;       // row group (4 rows each)
    int rowBase = blockIdx.x * GM_BM;

    float acc[4][8];
#pragma unroll
    for (int i = 0; i < 4; i++)
#pragma unroll
        for (int j = 0; j < 8; j++) acc[i][j] = 0.f;

    for (int k0 = 0; k0 < FIN; k0 += GM_BK) {
#pragma unroll
        for (int t = 0; t < 8; t++) {
            int idx = tid + t * 256;
            int r = idx >> 5, c = idx & 31;
            int gr = rowBase + r;
            Xs[r][c] = (gr < M) ? X[gr * FIN + k0 + c] : 0.f;
        }
#pragma unroll
        for (int t = 0; t < 16; t++) {
            int idx = tid + t * 256;
            int kk = idx >> 7, n = idx & 127;
            Ws[kk][n] = W[(k0 + kk) * F1 + n];
        }
        __syncthreads();
#pragma unroll
        for (int kk = 0; kk < GM_BK; kk++) {
            float xv[4];
#pragma unroll
            for (int i = 0; i < 4; i++) xv[i] = Xs[ty * 4 + i][kk];
            float4 w0 = *(const float4*)&Ws[kk][tx * 8];
            float4 w1 = *(const float4*)&Ws[kk][tx * 8 + 4];
            float wv[8] = {w0.x, w0.y, w0.z, w0.w, w1.x, w1.y, w1.z, w1.w};
#pragma unroll
            for (int i = 0; i < 4; i++)
#pragma unroll
                for (int j = 0; j < 8; j++) acc[i][j] += xv[i] * wv[j];
        }
        __syncthreads();
    }
#pragma unroll
    for (int i = 0; i < 4; i++) {
        int gr = rowBase + ty * 4 + i;
        if (gr < M) {
            float4 o0 = make_float4(acc[i][0], acc[i][1], acc[i][2], acc[i][3]);
            float4 o1 = make_float4(acc[i][4], acc[i][5], acc[i][6], acc[i][7]);
            *(float4*)&g_h1[gr * F1 + tx * 8]     = o0;
            *(float4*)&g_h1[gr * F1 + tx * 8 + 4] = o1;
        }
    }
}

// ------------------------- per-node attention dots (layer 1) -------------------------
__global__ void attdot_kernel(const float* __restrict__ att_s, const float* __restrict__ att_d) {
    int t = blockIdx.x * blockDim.x + threadIdx.x;
    int n = t >> 5;
    if (n >= N_NODES) return;
    int lane = t & 31;
    float4 hv = *(const float4*)&g_h1[n * F1 + lane * 4];
    float4 as = *(const float4*)&att_s[lane * 4];
    float4 ad = *(const float4*)&att_d[lane * 4];
    float ps = hv.x * as.x + hv.y * as.y + hv.z * as.z + hv.w * as.w;
    float pd = hv.x * ad.x + hv.y * ad.y + hv.z * ad.z + hv.w * ad.w;
    ps += __shfl_xor_sync(0xffffffffu, ps, 1);
    ps += __shfl_xor_sync(0xffffffffu, ps, 2);
    pd += __shfl_xor_sync(0xffffffffu, pd, 1);
    pd += __shfl_xor_sync(0xffffffffu, pd, 2);
    if ((lane & 3) == 0) {
        int h = lane >> 2;
        g_asrc[n * H1 + h] = ps;
        g_adst[n * H1 + h] = pd;
    }
}

// ------------------------- layer 1 edge passes -------------------------
__global__ void edge1_max_kernel(int ET) {
    int i = blockIdx.x * blockDim.x + threadIdx.x;
    if (i >= ET) return;
    int s = g_src[i], d = g_dst[i];
    float4 a0 = *(const float4*)&g_asrc[s * H1];
    float4 a1 = *(const float4*)&g_asrc[s * H1 + 4];
    float4 b0 = *(const float4*)&g_adst[d * H1];
    float4 b1 = *(const float4*)&g_adst[d * H1 + 4];
    float e[8] = {a0.x + b0.x, a0.y + b0.y, a0.z + b0.z, a0.w + b0.w,
                  a1.x + b1.x, a1.y + b1.y, a1.z + b1.z, a1.w + b1.w};
#pragma unroll
    for (int h = 0; h < 8; h++) {
        float v = e[h];
        v = v > 0.f ? v : NEG_SLOPE * v;
        e[h] = v;
        atomicMaxF(&g_m1[d * H1 + h], v);
    }
    *(float4*)&g_e1[i * 8]     = make_float4(e[0], e[1], e[2], e[3]);
    *(float4*)&g_e1[i * 8 + 4] = make_float4(e[4], e[5], e[6], e[7]);
}

__global__ void edge1_expsum_kernel(int ET) {
    int i = blockIdx.x * blockDim.x + threadIdx.x;
    if (i >= ET) return;
    int d = g_dst[i];
    float4 m0 = *(const float4*)&g_m1[d * H1];
    float4 m1 = *(const float4*)&g_m1[d * H1 + 4];
    float4 e0 = *(const float4*)&g_e1[i * 8];
    float4 e1 = *(const float4*)&g_e1[i * 8 + 4];
    float ee[8];
    ee[0] = expf(e0.x - m0.x); ee[1] = expf(e0.y - m0.y);
    ee[2] = expf(e0.z - m0.z); ee[3] = expf(e0.w - m0.w);
    ee[4] = expf(e1.x - m1.x); ee[5] = expf(e1.y - m1.y);
    ee[6] = expf(e1.z - m1.z); ee[7] = expf(e1.w - m1.w);
    *(float4*)&g_e1[i * 8]     = make_float4(ee[0], ee[1], ee[2], ee[3]);
    *(float4*)&g_e1[i * 8 + 4] = make_float4(ee[4], ee[5], ee[6], ee[7]);
    redAdd4(&g_s1[d * H1],     ee[0], ee[1], ee[2], ee[3]);
    redAdd4(&g_s1[d * H1 + 4], ee[4], ee[5], ee[6], ee[7]);
}

// one warp per edge: 128-float weighted scatter-add
__global__ void edge1_agg_kernel(int ET) {
    int t = blockIdx.x * blockDim.x + threadIdx.x;
    int i = t >> 5;
    if (i >= ET) return;
    int lane = t & 31;
    int s = g_src[i], d = g_dst[i];
    int h = lane >> 2;
    float alpha = g_e1[i * 8 + h] / g_s1[d * H1 + h];
    float4 hv = *(const float4*)&g_h1[s * F1 + lane * 4];
    redAdd4(&g_agg1[d * F1 + lane * 4],
            alpha * hv.x, alpha * hv.y, alpha * hv.z, alpha * hv.w);
}

// elu(agg + b1) in place
__global__ void elu_kernel(const float* __restrict__ b1) {
    int i = blockIdx.x * blockDim.x + threadIdx.x;
    if (i >= N_NODES * F1) return;
    float v = g_agg1[i] + b1[i & 127];
    g_agg1[i] = v > 0.f ? v : expm1f(v);
}

// ------------------------- layer 2: h2 = h1e @ W2 ([128,2]), attention dots -------------------------
__global__ void h2_kernel(const float* __restrict__ W2,
                          const float* __restrict__ as2, const float* __restrict__ ad2) {
    int t = blockIdx.x * blockDim.x + threadIdx.x;
    int n = t >> 5;
    if (n >= N_NODES) return;
    int lane = t & 31;
    float4 hv = *(const float4*)&g_agg1[n * F1 + lane * 4];
    const float4* W4 = (const float4*)W2;
    float4 wa = W4[lane * 2];       // (W[k0][0], W[k0][1], W[k1][0], W[k1][1])
    float4 wb = W4[lane * 2 + 1];   // (W[k2][0], W[k2][1], W[k3][0], W[k3][1])
    float p0 = hv.x * wa.x + hv.y * wa.z + hv.z * wb.x + hv.w * wb.z;
    float p1 = hv.x * wa.y + hv.y * wa.w + hv.z * wb.y + hv.w * wb.w;
#pragma unroll
    for (int o = 16; o > 0; o >>= 1) {
        p0 += __shfl_xor_sync(0xffffffffu, p0, o);
        p1 += __shfl_xor_sync(0xffffffffu, p1, o);
    }
    if (lane == 0) {
        g_h2[n * 2]     = p0;
        g_h2[n * 2 + 1] = p1;
        g_a2s[n] = p0 * as2[0] + p1 * as2[1];
        g_a2d[n] = p0 * ad2[0] + p1 * ad2[1];
    }
}

// ------------------------- layer 2 edge passes -------------------------
__global__ void edge2_max_kernel(int ET) {
    int i = blockIdx.x * blockDim.x + threadIdx.x;
    if (i >= ET) return;
    int s = g_src[i], d = g_dst[i];
    float v = g_a2s[s] + g_a2d[d];
    v = v > 0.f ? v : NEG_SLOPE * v;
    g_e2[i] = v;
    atomicMaxF(&g_m2[d], v);
}

__global__ void edge2_expsum_kernel(int ET) {
    int i = blockIdx.x * blockDim.x + threadIdx.x;
    if (i >= ET) return;
    int d = g_dst[i];
    float ee = expf(g_e2[i] - g_m2[d]);
    g_e2[i] = ee;
    atomicAdd(&g_s2[d], ee);
}

__global__ void edge2_agg_kernel(float* __restrict__ out, int ET) {
    int i = blockIdx.x * blockDim.x + threadIdx.x;
    if (i >= ET) return;
    int s = g_src[i], d = g_dst[i];
    float alpha = g_e2[i] / g_s2[d];
    redAdd2(&out[d * 2], alpha * g_h2[s * 2], alpha * g_h2[s * 2 + 1]);
}

// ------------------------- launch -------------------------
extern "C" void kernel_launch(void* const* d_in, const int* in_sizes, int n_in,
                              void* d_out, int out_size) {
    const float* x    = (const float*)d_in[0];
    const void*  ei   = d_in[1];
    const float* W1   = (const float*)d_in[2];
    const float* as1  = (const float*)d_in[3];
    const float* ad1  = (const float*)d_in[4];
    const float* b1   = (const float*)d_in[5];
    const float* W2   = (const float*)d_in[6];
    const float* as2  = (const float*)d_in[7];
    const float* ad2  = (const float*)d_in[8];
    const float* b2   = (const float*)d_in[9];
    float* out = (float*)d_out;

    int E  = in_sizes[1] / 2;
    int ET = E + N_NODES;

    probe_kernel<<<1, 256>>>(ei);
    convert_kernel<<<(ET + 255) / 256, 256>>>(ei, E, ET);
    init_kernel<<<(N_NODES * F1 + 255) / 256, 256>>>(out, b2);

    gemm1_kernel<<<(N_NODES + GM_BM - 1) / GM_BM, 256>>>(x, W1, N_NODES);
    attdot_kernel<<<(N_NODES * 32 + 255) / 256, 256>>>(as1, ad1);

    edge1_max_kernel<<<(ET + 255) / 256, 256>>>(ET);
    edge1_expsum_kernel<<<(ET + 255) / 256, 256>>>(ET);
    {
        long long tot = (long long)ET * 32;
        edge1_agg_kernel<<<(unsigned)((tot + 255) / 256), 256>>>(ET);
    }
    elu_kernel<<<(N_NODES * F1 + 255) / 256, 256>>>(b1);

    h2_kernel<<<(N_NODES * 32 + 255) / 256, 256>>>(W2, as2, ad2);
    edge2_max_kernel<<<(ET + 255) / 256, 256>>>(ET);
    edge2_expsum_kernel<<<(ET + 255) / 256, 256>>>(ET);
    edge2_agg_kernel<<<(ET + 255) / 256, 256>>>(out, ET);
}

// round 2
// speedup vs baseline: 1.5292x; 1.5292x over previous
#include <cuda_runtime.h>
#include <math.h>

#define N_NODES 50000
#define FIN 128
#define H1 8
#define F1 128
#define E_MAX 800000
#define ET_MAX (E_MAX + N_NODES)
#define NEG_SLOPE 0.2f
#define NEG_INF __int_as_float(0xff800000)

// ------------------------- scratch -------------------------
__device__ float g_h1[N_NODES * F1];
__device__ float g_agg1[N_NODES * F1];
__device__ float g_asrc[N_NODES * H1];
__device__ float g_adst[N_NODES * H1];
__device__ float g_h2[N_NODES * 2];
__device__ float g_a2s[N_NODES];
__device__ float g_a2d[N_NODES];
__device__ int   g_src[ET_MAX];
__device__ int   g_dst[ET_MAX];
__device__ int   g_csr_src[ET_MAX];
__device__ int   g_start[N_NODES + 1];
__device__ int   g_deg[N_NODES];
__device__ int   g_cnt[N_NODES];
__device__ int   g_is64;

__device__ __forceinline__ float leaky(float v) { return v > 0.f ? v : NEG_SLOPE * v; }

// ------------------------- dtype probe -------------------------
__global__ void probe_kernel(const void* ei) {
    const long long* p = (const long long*)ei;
    int bad = 0;
    for (int i = threadIdx.x; i < 2048; i += 256) {
        long long v = p[i];
        if (v < 0 || v >= (long long)N_NODES) bad = 1;
    }
    bad = __syncthreads_or(bad);
    if (threadIdx.x == 0) g_is64 = bad ? 0 : 1;
}

__global__ void zero_kernel() {
    int i = blockIdx.x * blockDim.x + threadIdx.x;
    if (i < N_NODES) { g_deg[i] = 0; g_cnt[i] = 0; }
}

// convert + self loops + dst histogram
__global__ void convert_kernel(const void* ei, int E, int ET) {
    int i = blockIdx.x * blockDim.x + threadIdx.x;
    if (i >= ET) return;
    int s, d;
    if (i < E) {
        if (g_is64) {
            const long long* p = (const long long*)ei;
            s = (int)p[i]; d = (int)p[E + i];
        } else {
            const int* p = (const int*)ei;
            s = p[i]; d = p[E + i];
        }
    } else {
        s = d = i - E;
    }
    g_src[i] = s;
    g_dst[i] = d;
    atomicAdd(&g_deg[d], 1);
}

// single-block exclusive scan of g_deg[50000] -> g_start[50001]
__global__ void scan_kernel() {
    __shared__ int sums[1024];
    const int CH = 49;  // 1024*49 = 50176 >= 50000
    int t = threadIdx.x;
    int base = t * CH;
    int vals[CH];
    int local = 0;
#pragma unroll
    for (int i = 0; i < CH; i++) {
        int idx = base + i;
        int v = (idx < N_NODES) ? g_deg[idx] : 0;
        vals[i] = local;
        local += v;
    }
    sums[t] = local;
    __syncthreads();
    for (int off = 1; off < 1024; off <<= 1) {
        int v = (t >= off) ? sums[t - off] : 0;
        __syncthreads();
        sums[t] += v;
        __syncthreads();
    }
    int excl = (t == 0) ? 0 : sums[t - 1];
#pragma unroll
    for (int i = 0; i < CH; i++) {
        int idx = base + i;
        if (idx < N_NODES) g_start[idx] = excl + vals[i];
    }
    if (t == 0) g_start[N_NODES] = sums[1023];
}

__global__ void scatter_kernel(int ET) {
    int i = blockIdx.x * blockDim.x + threadIdx.x;
    if (i >= ET) return;
    int d = g_dst[i];
    int pos = g_start[d] + atomicAdd(&g_cnt[d], 1);
    g_csr_src[pos] = g_src[i];
}

// ------------------------- GEMM: h1 = x @ W1 (M x 128 x 128), fused attdot epilogue -------------------------
#define GM_BM 64
#define GM_BK 32
__global__ void gemm1_kernel(const float* __restrict__ X, const float* __restrict__ W,
                             const float* __restrict__ att_s, const float* __restrict__ att_d,
                             int M) {
    __shared__ __align__(16) float Xs[GM_BM][GM_BK + 1];
    __shared__ __align__(16) float Ws[GM_BK][F1 + 4];
    __shared__ float s_as[F1], s_ad[F1];
    int tid = threadIdx.x;
    int tx = tid & 15;
    int ty = tid >> 4;
    int rowBase = blockIdx.x * GM_BM;

    if (tid < F1) { s_as[tid] = att_s[tid]; s_ad[tid] = att_d[tid]; }

    float acc[4][8];
#pragma unroll
    for (int i = 0; i < 4; i++)
#pragma unroll
        for (int j = 0; j < 8; j++) acc[i][j] = 0.f;

    for (int k0 = 0; k0 < FIN; k0 += GM_BK) {
#pragma unroll
        for (int t = 0; t < 8; t++) {
            int idx = tid + t * 256;
            int r = idx >> 5, c = idx & 31;
            int gr = rowBase + r;
            Xs[r][c] = (gr < M) ? X[gr * FIN + k0 + c] : 0.f;
        }
#pragma unroll
        for (int t = 0; t < 16; t++) {
            int idx = tid + t * 256;
            int kk = idx >> 7, n = idx & 127;
            Ws[kk][n] = W[(k0 + kk) * F1 + n];
        }
        __syncthreads();
#pragma unroll
        for (int kk = 0; kk < GM_BK; kk++) {
            float xv[4];
#pragma unroll
            for (int i = 0; i < 4; i++) xv[i] = Xs[ty * 4 + i][kk];
            float4 w0 = *(const float4*)&Ws[kk][tx * 8];
            float4 w1 = *(const float4*)&Ws[kk][tx * 8 + 4];
            float wv[8] = {w0.x, w0.y, w0.z, w0.w, w1.x, w1.y, w1.z, w1.w};
#pragma unroll
            for (int i = 0; i < 4; i++)
#pragma unroll
                for (int j = 0; j < 8; j++) acc[i][j] += xv[i] * wv[j];
        }
        __syncthreads();
    }
    // store h1 tile
#pragma unroll
    for (int i = 0; i < 4; i++) {
        int gr = rowBase + ty * 4 + i;
        if (gr < M) {
            *(float4*)&g_h1[gr * F1 + tx * 8]     = make_float4(acc[i][0], acc[i][1], acc[i][2], acc[i][3]);
            *(float4*)&g_h1[gr * F1 + tx * 8 + 4] = make_float4(acc[i][4], acc[i][5], acc[i][6], acc[i][7]);
        }
    }
    // fused attention dots: head = tx>>1, cols tx*8..tx*8+7 map to att[head][(tx&1)*8 + j]
    int head = tx >> 1;
    int cbase = head * 16 + (tx & 1) * 8;
#pragma unroll
    for (int i = 0; i < 4; i++) {
        float ps = 0.f, pd = 0.f;
#pragma unroll
        for (int j = 0; j < 8; j++) {
            ps += acc[i][j] * s_as[cbase + j];
            pd += acc[i][j] * s_ad[cbase + j];
        }
        ps += __shfl_xor_sync(0xffffffffu, ps, 1);
        pd += __shfl_xor_sync(0xffffffffu, pd, 1);
        if ((tx & 1) == 0) {
            int gr = rowBase + ty * 4 + i;
            if (gr < M) {
                g_asrc[gr * H1 + head] = ps;
                g_adst[gr * H1 + head] = pd;
            }
        }
    }
}

// ------------------------- fused layer-1 softmax + aggregation: one warp per dst node -------------------------
__global__ void node1_kernel() {
    int n = (blockIdx.x * blockDim.x + threadIdx.x) >> 5;
    if (n >= N_NODES) return;
    int lane = threadIdx.x & 31;
    int rs = g_start[n], re = g_start[n + 1];

    float4 ad0 = *(const float4*)&g_adst[n * H1];
    float4 ad1 = *(const float4*)&g_adst[n * H1 + 4];
    float adh[8] = {ad0.x, ad0.y, ad0.z, ad0.w, ad1.x, ad1.y, ad1.z, ad1.w};

    // pass 1: per-head max (lane-parallel over edges)
    float m[8];
#pragma unroll
    for (int h = 0; h < 8; h++) m[h] = NEG_INF;
    for (int j = rs + lane; j < re; j += 32) {
        int s = g_csr_src[j];
        float4 a0 = *(const float4*)&g_asrc[s * H1];
        float4 a1 = *(const float4*)&g_asrc[s * H1 + 4];
        float ev[8] = {a0.x + adh[0], a0.y + adh[1], a0.z + adh[2], a0.w + adh[3],
                       a1.x + adh[4], a1.y + adh[5], a1.z + adh[6], a1.w + adh[7]};
#pragma unroll
        for (int h = 0; h < 8; h++) m[h] = fmaxf(m[h], leaky(ev[h]));
    }
#pragma unroll
    for (int o = 16; o > 0; o >>= 1)
#pragma unroll
        for (int h = 0; h < 8; h++) m[h] = fmaxf(m[h], __shfl_xor_sync(0xffffffffu, m[h], o));

    // pass 2: serial over edges; lane covers features [lane*4, lane*4+4), head = lane>>2
    int myh = lane >> 2;
    float mh = m[myh];
    float adm = adh[myh];
    float ssum = 0.f;
    float acc0 = 0.f, acc1 = 0.f, acc2 = 0.f, acc3 = 0.f;

    int j = rs;
    for (; j + 1 < re; j += 2) {
        int s0 = g_csr_src[j];
        int s1 = g_csr_src[j + 1];
        float av0 = __ldg(&g_asrc[s0 * H1 + myh]);
        float av1 = __ldg(&g_asrc[s1 * H1 + myh]);
        float4 hv0 = *(const float4*)&g_h1[(size_t)s0 * F1 + lane * 4];
        float4 hv1 = *(const float4*)&g_h1[(size_t)s1 * F1 + lane * 4];
        float ee0 = __expf(leaky(av0 + adm) - mh);
        float ee1 = __expf(leaky(av1 + adm) - mh);
        ssum += ee0 + ee1;
        acc0 += ee0 * hv0.x + ee1 * hv1.x;
        acc1 += ee0 * hv0.y + ee1 * hv1.y;
        acc2 += ee0 * hv0.z + ee1 * hv1.z;
        acc3 += ee0 * hv0.w + ee1 * hv1.w;
    }
    if (j < re) {
        int s0 = g_csr_src[j];
        float av0 = __ldg(&g_asrc[s0 * H1 + myh]);
        float4 hv0 = *(const float4*)&g_h1[(size_t)s0 * F1 + lane * 4];
        float ee0 = __expf(leaky(av0 + adm) - mh);
        ssum += ee0;
        acc0 += ee0 * hv0.x; acc1 += ee0 * hv0.y; acc2 += ee0 * hv0.z; acc3 += ee0 * hv0.w;
    }
    float inv = 1.f / ssum;
    *(float4*)&g_agg1[(size_t)n * F1 + lane * 4] =
        make_float4(acc0 * inv, acc1 * inv, acc2 * inv, acc3 * inv);
}

// ------------------------- layer 2 projection: elu(agg+b1) @ W2, attention dots -------------------------
__global__ void h2_kernel(const float* __restrict__ b1, const float* __restrict__ W2,
                          const float* __restrict__ as2, const float* __restrict__ ad2) {
    int n = (blockIdx.x * blockDim.x + threadIdx.x) >> 5;
    if (n >= N_NODES) return;
    int lane = threadIdx.x & 31;
    float4 hv = *(const float4*)&g_agg1[(size_t)n * F1 + lane * 4];
    float4 bv = *(const float4*)&b1[lane * 4];
    float v0 = hv.x + bv.x, v1 = hv.y + bv.y, v2 = hv.z + bv.z, v3 = hv.w + bv.w;
    v0 = v0 > 0.f ? v0 : expm1f(v0);
    v1 = v1 > 0.f ? v1 : expm1f(v1);
    v2 = v2 > 0.f ? v2 : expm1f(v2);
    v3 = v3 > 0.f ? v3 : expm1f(v3);
    const float4* W4 = (const float4*)W2;
    float4 wa = W4[lane * 2];
    float4 wb = W4[lane * 2 + 1];
    float p0 = v0 * wa.x + v1 * wa.z + v2 * wb.x + v3 * wb.z;
    float p1 = v0 * wa.y + v1 * wa.w + v2 * wb.y + v3 * wb.w;
#pragma unroll
    for (int o = 16; o > 0; o >>= 1) {
        p0 += __shfl_xor_sync(0xffffffffu, p0, o);
        p1 += __shfl_xor_sync(0xffffffffu, p1, o);
    }
    if (lane == 0) {
        g_h2[n * 2] = p0;
        g_h2[n * 2 + 1] = p1;
        g_a2s[n] = p0 * as2[0] + p1 * as2[1];
        g_a2d[n] = p0 * ad2[0] + p1 * ad2[1];
    }
}

// ------------------------- fused layer-2: one warp per node, single-pass softmax-aggregate -------------------------
__global__ void node2_kernel(float* __restrict__ out, const float* __restrict__ b2) {
    int n = (blockIdx.x * blockDim.x + threadIdx.x) >> 5;
    if (n >= N_NODES) return;
    int lane = threadIdx.x & 31;
    int rs = g_start[n], re = g_start[n + 1];
    float a2dn = g_a2d[n];

    float m = NEG_INF;
    for (int j = rs + lane; j < re; j += 32)
        m = fmaxf(m, leaky(g_a2s[g_csr_src[j]] + a2dn));
#pragma unroll
    for (int o = 16; o > 0; o >>= 1) m = fmaxf(m, __shfl_xor_sync(0xffffffffu, m, o));

    float S = 0.f, n0 = 0.f, n1 = 0.f;
    for (int j = rs + lane; j < re; j += 32) {
        int s = g_csr_src[j];
        float ee = __expf(leaky(g_a2s[s] + a2dn) - m);
        float2 h = *(const float2*)&g_h2[s * 2];
        S += ee; n0 += ee * h.x; n1 += ee * h.y;
    }
#pragma unroll
    for (int o = 16; o > 0; o >>= 1) {
        S  += __shfl_xor_sync(0xffffffffu, S, o);
        n0 += __shfl_xor_sync(0xffffffffu, n0, o);
        n1 += __shfl_xor_sync(0xffffffffu, n1, o);
    }
    if (lane == 0) {
        float inv = 1.f / S;
        out[n * 2]     = n0 * inv + b2[0];
        out[n * 2 + 1] = n1 * inv + b2[1];
    }
}

// ------------------------- launch -------------------------
extern "C" void kernel_launch(void* const* d_in, const int* in_sizes, int n_in,
                              void* d_out, int out_size) {
    const float* x   = (const float*)d_in[0];
    const void*  ei  = d_in[1];
    const float* W1  = (const float*)d_in[2];
    const float* as1 = (const float*)d_in[3];
    const float* ad1 = (const float*)d_in[4];
    const float* b1  = (const float*)d_in[5];
    const float* W2  = (const float*)d_in[6];
    const float* as2 = (const float*)d_in[7];
    const float* ad2 = (const float*)d_in[8];
    const float* b2  = (const float*)d_in[9];
    float* out = (float*)d_out;

    int E  = in_sizes[1] / 2;
    int ET = E + N_NODES;

    probe_kernel<<<1, 256>>>(ei);
    zero_kernel<<<(N_NODES + 255) / 256, 256>>>();
    convert_kernel<<<(ET + 255) / 256, 256>>>(ei, E, ET);
    scan_kernel<<<1, 1024>>>();
    scatter_kernel<<<(ET + 255) / 256, 256>>>(ET);

    gemm1_kernel<<<(N_NODES + GM_BM - 1) / GM_BM, 256>>>(x, W1, as1, ad1, N_NODES);

    int nodeBlocks = (N_NODES * 32 + 255) / 256;
    node1_kernel<<<nodeBlocks, 256>>>();
    h2_kernel<<<nodeBlocks, 256>>>(b1, W2, as2, ad2);
    node2_kernel<<<nodeBlocks, 256>>>(out, b2);
}

// round 3
// speedup vs baseline: 1.8312x; 1.1975x over previous
#include <cuda_runtime.h>
#include <math.h>

#define N_NODES 50000
#define FIN 128
#define H1 8
#define F1 128
#define E_MAX 800000
#define ET_MAX (E_MAX + N_NODES)
#define NEG_SLOPE 0.2f
#define NEG_INF __int_as_float(0xff800000)
#define SCAN_NB ((N_NODES + 1023) / 1024)   // 49

// ------------------------- scratch -------------------------
__device__ float g_h1[N_NODES * F1];
__device__ float g_agg1[N_NODES * F1];
__device__ float g_asrc[N_NODES * H1];
__device__ float g_adst[N_NODES * H1];
__device__ float g_h2[N_NODES * 2];
__device__ float g_a2s[N_NODES];
__device__ float g_a2d[N_NODES];
__device__ int   g_src[ET_MAX];
__device__ int   g_dst[ET_MAX];
__device__ int   g_csr_src[ET_MAX];
__device__ int   g_start[N_NODES + 1];
__device__ int   g_deg[N_NODES];
__device__ int   g_cnt[N_NODES];
__device__ int   g_bsum[SCAN_NB];
__device__ int   g_boff[SCAN_NB];
__device__ int   g_is64;

__device__ __forceinline__ float leaky(float v) { return v > 0.f ? v : NEG_SLOPE * v; }

// ------------------------- dtype probe -------------------------
__global__ void probe_kernel(const void* ei) {
    const long long* p = (const long long*)ei;
    int bad = 0;
    for (int i = threadIdx.x; i < 2048; i += 256) {
        long long v = p[i];
        if (v < 0 || v >= (long long)N_NODES) bad = 1;
    }
    bad = __syncthreads_or(bad);
    if (threadIdx.x == 0) g_is64 = bad ? 0 : 1;
}

__global__ void zero_kernel() {
    int i = blockIdx.x * blockDim.x + threadIdx.x;
    if (i < N_NODES) { g_deg[i] = 0; g_cnt[i] = 0; }
}

// convert + self loops + dst histogram
__global__ void convert_kernel(const void* ei, int E, int ET) {
    int i = blockIdx.x * blockDim.x + threadIdx.x;
    if (i >= ET) return;
    int s, d;
    if (i < E) {
        if (g_is64) {
            const long long* p = (const long long*)ei;
            s = (int)p[i]; d = (int)p[E + i];
        } else {
            const int* p = (const int*)ei;
            s = p[i]; d = p[E + i];
        }
    } else {
        s = d = i - E;
    }
    g_src[i] = s;
    g_dst[i] = d;
    atomicAdd(&g_deg[d], 1);
}

// ------------------------- multi-block scan -------------------------
__global__ void scanA_kernel() {
    int i = blockIdx.x * 1024 + threadIdx.x;
    int v = (i < N_NODES) ? g_deg[i] : 0;
    int lane = threadIdx.x & 31, wid = threadIdx.x >> 5;
    int x = v;
#pragma unroll
    for (int o = 1; o < 32; o <<= 1) {
        int t = __shfl_up_sync(0xffffffffu, x, o);
        if (lane >= o) x += t;
    }
    __shared__ int wsum[32];
    if (lane == 31) wsum[wid] = x;
    __syncthreads();
    if (wid == 0) {
        int y = wsum[lane];
#pragma unroll
        for (int o = 1; o < 32; o <<= 1) {
            int t = __shfl_up_sync(0xffffffffu, y, o);
            if (lane >= o) y += t;
        }
        wsum[lane] = y;
    }
    __syncthreads();
    int incl = x + (wid > 0 ? wsum[wid - 1] : 0);
    if (i < N_NODES) g_start[i] = incl - v;            // block-local exclusive
    if (threadIdx.x == 1023) g_bsum[blockIdx.x] = incl; // block total
}

__global__ void scanB_kernel() {
    int lane = threadIdx.x;  // 32 threads
    int i0 = 2 * lane, i1 = 2 * lane + 1;
    int a = (i0 < SCAN_NB) ? g_bsum[i0] : 0;
    int b = (i1 < SCAN_NB) ? g_bsum[i1] : 0;
    int loc = a + b;
    int x = loc;
#pragma unroll
    for (int o = 1; o < 32; o <<= 1) {
        int t = __shfl_up_sync(0xffffffffu, x, o);
        if (lane >= o) x += t;
    }
    int excl = x - loc;
    if (i0 < SCAN_NB) g_boff[i0] = excl;
    if (i1 < SCAN_NB) g_boff[i1] = excl + a;
    if (lane == 31) g_start[N_NODES] = x;  // grand total
}

__global__ void scanC_kernel() {
    int i = blockIdx.x * blockDim.x + threadIdx.x;
    if (i < N_NODES) g_start[i] += g_boff[i >> 10];
}

__global__ void scatter_kernel(int ET) {
    int i = blockIdx.x * blockDim.x + threadIdx.x;
    if (i >= ET) return;
    int d = g_dst[i];
    int pos = g_start[d] + atomicAdd(&g_cnt[d], 1);
    g_csr_src[pos] = g_src[i];
}

// ------------------------- GEMM: h1 = x @ W1 (M x 128 x 128), 128x128 tile, 8x8 micro -------------------------
#define BM 128
#define BK 8
__global__ void __launch_bounds__(256, 2)
gemm1_kernel(const float* __restrict__ X, const float* __restrict__ W,
             const float* __restrict__ att_s, const float* __restrict__ att_d, int M) {
    __shared__ __align__(16) float As[BK][BM];       // X^T tile
    __shared__ __align__(16) float Bs[BK][F1];       // W tile
    __shared__ float s_as[F1], s_ad[F1];
    int tid = threadIdx.x;
    int tx = tid & 15;          // col group: 8 cols each
    int ty = tid >> 4;          // row group: 8 rows each
    int rowBase = blockIdx.x * BM;

    if (tid < F1) { s_as[tid] = att_s[tid]; s_ad[tid] = att_d[tid]; }

    // load indices for global tiles
    int lrow = tid >> 1;            // 0..127 (X row within tile)
    int lhalf = tid & 1;            // which float4 of the 8-wide k strip
    int grow = rowBase + lrow;
    const float* Xrow = X + (size_t)grow * FIN;
    int wrow = tid >> 5;            // 0..7 (k within tile)
    int wcol = (tid & 31) * 4;      // 0..124

    float acc[8][8];
#pragma unroll
    for (int i = 0; i < 8; i++)
#pragma unroll
        for (int j = 0; j < 8; j++) acc[i][j] = 0.f;

    for (int k0 = 0; k0 < FIN; k0 += BK) {
        // X tile: 128 rows x 8 k, transposed into As[k][m]
        float4 xv = make_float4(0.f, 0.f, 0.f, 0.f);
        if (grow < M) xv = *(const float4*)(Xrow + k0 + lhalf * 4);
        As[lhalf * 4 + 0][lrow] = xv.x;
        As[lhalf * 4 + 1][lrow] = xv.y;
        As[lhalf * 4 + 2][lrow] = xv.z;
        As[lhalf * 4 + 3][lrow] = xv.w;
        // W tile: 8 k x 128 n
        *(float4*)&Bs[wrow][wcol] = *(const float4*)&W[(size_t)(k0 + wrow) * F1 + wcol];
        __syncthreads();
#pragma unroll
        for (int kk = 0; kk < BK; kk++) {
            float4 a0 = *(const float4*)&As[kk][ty * 8];
            float4 a1 = *(const float4*)&As[kk][ty * 8 + 4];
            float4 b0 = *(const float4*)&Bs[kk][tx * 8];
            float4 b1 = *(const float4*)&Bs[kk][tx * 8 + 4];
            float av[8] = {a0.x, a0.y, a0.z, a0.w, a1.x, a1.y, a1.z, a1.w};
            float bv[8] = {b0.x, b0.y, b0.z, b0.w, b1.x, b1.y, b1.z, b1.w};
#pragma unroll
            for (int i = 0; i < 8; i++)
#pragma unroll
                for (int j = 0; j < 8; j++) acc[i][j] += av[i] * bv[j];
        }
        __syncthreads();
    }

    // epilogue: store h1 + fused attention dots
    int head = tx >> 1;
    int cbase = head * 16 + (tx & 1) * 8;
#pragma unroll
    for (int i = 0; i < 8; i++) {
        int gr = rowBase + ty * 8 + i;
        if (gr < M) {
            *(float4*)&g_h1[(size_t)gr * F1 + tx * 8] =
                make_float4(acc[i][0], acc[i][1], acc[i][2], acc[i][3]);
            *(float4*)&g_h1[(size_t)gr * F1 + tx * 8 + 4] =
                make_float4(acc[i][4], acc[i][5], acc[i][6], acc[i][7]);
        }
        float ps = 0.f, pd = 0.f;
#pragma unroll
        for (int j = 0; j < 8; j++) {
            ps += acc[i][j] * s_as[cbase + j];
            pd += acc[i][j] * s_ad[cbase + j];
        }
        ps += __shfl_xor_sync(0xffffffffu, ps, 1);
        pd += __shfl_xor_sync(0xffffffffu, pd, 1);
        if ((tx & 1) == 0 && gr < M) {
            g_asrc[gr * H1 + head] = ps;
            g_adst[gr * H1 + head] = pd;
        }
    }
}

// ------------------------- fused layer-1 softmax + aggregation: one warp per dst node -------------------------
__global__ void node1_kernel() {
    int n = (blockIdx.x * blockDim.x + threadIdx.x) >> 5;
    if (n >= N_NODES) return;
    int lane = threadIdx.x & 31;
    int rs = g_start[n], re = g_start[n + 1];

    float4 ad0 = *(const float4*)&g_adst[n * H1];
    float4 ad1 = *(const float4*)&g_adst[n * H1 + 4];
    float adh[8] = {ad0.x, ad0.y, ad0.z, ad0.w, ad1.x, ad1.y, ad1.z, ad1.w};

    float m[8];
#pragma unroll
    for (int h = 0; h < 8; h++) m[h] = NEG_INF;
    for (int j = rs + lane; j < re; j += 32) {
        int s = g_csr_src[j];
        float4 a0 = *(const float4*)&g_asrc[s * H1];
        float4 a1 = *(const float4*)&g_asrc[s * H1 + 4];
        float ev[8] = {a0.x + adh[0], a0.y + adh[1], a0.z + adh[2], a0.w + adh[3],
                       a1.x + adh[4], a1.y + adh[5], a1.z + adh[6], a1.w + adh[7]};
#pragma unroll
        for (int h = 0; h < 8; h++) m[h] = fmaxf(m[h], leaky(ev[h]));
    }
#pragma unroll
    for (int o = 16; o > 0; o >>= 1)
#pragma unroll
        for (int h = 0; h < 8; h++) m[h] = fmaxf(m[h], __shfl_xor_sync(0xffffffffu, m[h], o));

    int myh = lane >> 2;
    float mh = m[myh];
    float adm = adh[myh];
    float ssum = 0.f;
    float acc0 = 0.f, acc1 = 0.f, acc2 = 0.f, acc3 = 0.f;

    int j = rs;
    for (; j + 1 < re; j += 2) {
        int s0 = g_csr_src[j];
        int s1 = g_csr_src[j + 1];
        float av0 = __ldg(&g_asrc[s0 * H1 + myh]);
        float av1 = __ldg(&g_asrc[s1 * H1 + myh]);
        float4 hv0 = *(const float4*)&g_h1[(size_t)s0 * F1 + lane * 4];
        float4 hv1 = *(const float4*)&g_h1[(size_t)s1 * F1 + lane * 4];
        float ee0 = __expf(leaky(av0 + adm) - mh);
        float ee1 = __expf(leaky(av1 + adm) - mh);
        ssum += ee0 + ee1;
        acc0 += ee0 * hv0.x + ee1 * hv1.x;
        acc1 += ee0 * hv0.y + ee1 * hv1.y;
        acc2 += ee0 * hv0.z + ee1 * hv1.z;
        acc3 += ee0 * hv0.w + ee1 * hv1.w;
    }
    if (j < re) {
        int s0 = g_csr_src[j];
        float av0 = __ldg(&g_asrc[s0 * H1 + myh]);
        float4 hv0 = *(const float4*)&g_h1[(size_t)s0 * F1 + lane * 4];
        float ee0 = __expf(leaky(av0 + adm) - mh);
        ssum += ee0;
        acc0 += ee0 * hv0.x; acc1 += ee0 * hv0.y; acc2 += ee0 * hv0.z; acc3 += ee0 * hv0.w;
    }
    float inv = 1.f / ssum;
    *(float4*)&g_agg1[(size_t)n * F1 + lane * 4] =
        make_float4(acc0 * inv, acc1 * inv, acc2 * inv, acc3 * inv);
}

// ------------------------- layer 2 projection -------------------------
__global__ void h2_kernel(const float* __restrict__ b1, const float* __restrict__ W2,
                          const float* __restrict__ as2, const float* __restrict__ ad2) {
    int n = (blockIdx.x * blockDim.x + threadIdx.x) >> 5;
    if (n >= N_NODES) return;
    int lane = threadIdx.x & 31;
    float4 hv = *(const float4*)&g_agg1[(size_t)n * F1 + lane * 4];
    float4 bv = *(const float4*)&b1[lane * 4];
    float v0 = hv.x + bv.x, v1 = hv.y + bv.y, v2 = hv.z + bv.z, v3 = hv.w + bv.w;
    v0 = v0 > 0.f ? v0 : expm1f(v0);
    v1 = v1 > 0.f ? v1 : expm1f(v1);
    v2 = v2 > 0.f ? v2 : expm1f(v2);
    v3 = v3 > 0.f ? v3 : expm1f(v3);
    const float4* W4 = (const float4*)W2;
    float4 wa = W4[lane * 2];
    float4 wb = W4[lane * 2 + 1];
    float p0 = v0 * wa.x + v1 * wa.z + v2 * wb.x + v3 * wb.z;
    float p1 = v0 * wa.y + v1 * wa.w + v2 * wb.y + v3 * wb.w;
#pragma unroll
    for (int o = 16; o > 0; o >>= 1) {
        p0 += __shfl_xor_sync(0xffffffffu, p0, o);
        p1 += __shfl_xor_sync(0xffffffffu, p1, o);
    }
    if (lane == 0) {
        g_h2[n * 2] = p0;
        g_h2[n * 2 + 1] = p1;
        g_a2s[n] = p0 * as2[0] + p1 * as2[1];
        g_a2d[n] = p0 * ad2[0] + p1 * ad2[1];
    }
}

// ------------------------- fused layer-2 softmax-aggregate -------------------------
__global__ void node2_kernel(float* __restrict__ out, const float* __restrict__ b2) {
    int n = (blockIdx.x * blockDim.x + threadIdx.x) >> 5;
    if (n >= N_NODES) return;
    int lane = threadIdx.x & 31;
    int rs = g_start[n], re = g_start[n + 1];
    float a2dn = g_a2d[n];

    float m = NEG_INF;
    for (int j = rs + lane; j < re; j += 32)
        m = fmaxf(m, leaky(g_a2s[g_csr_src[j]] + a2dn));
#pragma unroll
    for (int o = 16; o > 0; o >>= 1) m = fmaxf(m, __shfl_xor_sync(0xffffffffu, m, o));

    float S = 0.f, n0 = 0.f, n1 = 0.f;
    for (int j = rs + lane; j < re; j += 32) {
        int s = g_csr_src[j];
        float ee = __expf(leaky(g_a2s[s] + a2dn) - m);
        float2 h = *(const float2*)&g_h2[s * 2];
        S += ee; n0 += ee * h.x; n1 += ee * h.y;
    }
#pragma unroll
    for (int o = 16; o > 0; o >>= 1) {
        S  += __shfl_xor_sync(0xffffffffu, S, o);
        n0 += __shfl_xor_sync(0xffffffffu, n0, o);
        n1 += __shfl_xor_sync(0xffffffffu, n1, o);
    }
    if (lane == 0) {
        float inv = 1.f / S;
        out[n * 2]     = n0 * inv + b2[0];
        out[n * 2 + 1] = n1 * inv + b2[1];
    }
}

// ------------------------- launch -------------------------
extern "C" void kernel_launch(void* const* d_in, const int* in_sizes, int n_in,
                              void* d_out, int out_size) {
    const float* x   = (const float*)d_in[0];
    const void*  ei  = d_in[1];
    const float* W1  = (const float*)d_in[2];
    const float* as1 = (const float*)d_in[3];
    const float* ad1 = (const float*)d_in[4];
    const float* b1  = (const float*)d_in[5];
    const float* W2  = (const float*)d_in[6];
    const float* as2 = (const float*)d_in[7];
    const float* ad2 = (const float*)d_in[8];
    const float* b2  = (const float*)d_in[9];
    float* out = (float*)d_out;

    int E  = in_sizes[1] / 2;
    int ET = E + N_NODES;

    probe_kernel<<<1, 256>>>(ei);
    zero_kernel<<<(N_NODES + 255) / 256, 256>>>();
    convert_kernel<<<(ET + 255) / 256, 256>>>(ei, E, ET);
    scanA_kernel<<<SCAN_NB, 1024>>>();
    scanB_kernel<<<1, 32>>>();
    scanC_kernel<<<(N_NODES + 255) / 256, 256>>>();
    scatter_kernel<<<(ET + 255) / 256, 256>>>(ET);

    gemm1_kernel<<<(N_NODES + BM - 1) / BM, 256>>>(x, W1, as1, ad1, N_NODES);

    int nodeBlocks = (N_NODES * 32 + 255) / 256;
    node1_kernel<<<nodeBlocks, 256>>>();
    h2_kernel<<<nodeBlocks, 256>>>(b1, W2, as2, ad2);
    node2_kernel<<<nodeBlocks, 256>>>(out, b2);
}